// round 14
// baseline (speedup 1.0000x reference)
#include <cuda_runtime.h>
#include <cuda_fp16.h>
#include <cstdint>

#define B_   4
#define N_   2048
#define DIM_ 1024
#define H_   16
#define HD_  64
#define E3_  3072
#define M_   8192
#define SCALE_ 0.125f
#define LOG2E_ 1.44269504f

// fp16 scratch
__device__ __half g_xh[(size_t)M_ * DIM_];
__device__ __half g_wh[(size_t)E3_ * DIM_];
__device__ __half g_q[(size_t)B_ * H_ * N_ * HD_];   // pre-scaled by SCALE_*LOG2E_
__device__ __half g_k[(size_t)B_ * H_ * N_ * HD_];
__device__ __half g_v[(size_t)B_ * H_ * N_ * HD_];

// ---------------------------------------------------------------------------
// helpers
// ---------------------------------------------------------------------------
__device__ __forceinline__ uint32_t smem_u32(const void* p) {
    uint32_t a;
    asm("{ .reg .u64 t; cvta.to.shared.u64 t, %1; cvt.u32.u64 %0, t; }"
        : "=r"(a) : "l"(p));
    return a;
}
__device__ __forceinline__ void cpasync16(uint32_t dst, const void* src) {
    asm volatile("cp.async.cg.shared.global [%0], [%1], 16;"
                 :: "r"(dst), "l"(src) : "memory");
}
__device__ __forceinline__ void mma16(float* d,
                                      uint32_t a0, uint32_t a1, uint32_t a2, uint32_t a3,
                                      uint32_t b0, uint32_t b1) {
    asm volatile(
        "mma.sync.aligned.m16n8k16.row.col.f32.f16.f16.f32 "
        "{%0,%1,%2,%3}, {%4,%5,%6,%7}, {%8,%9}, {%0,%1,%2,%3};"
        : "+f"(d[0]), "+f"(d[1]), "+f"(d[2]), "+f"(d[3])
        : "r"(a0), "r"(a1), "r"(a2), "r"(a3), "r"(b0), "r"(b1));
}
__device__ __forceinline__ void ldsm_x4(uint32_t* r, uint32_t addr) {
    asm volatile("ldmatrix.sync.aligned.m8n8.x4.shared.b16 {%0,%1,%2,%3}, [%4];"
                 : "=r"(r[0]), "=r"(r[1]), "=r"(r[2]), "=r"(r[3]) : "r"(addr));
}
__device__ __forceinline__ void ldsm_x4t(uint32_t* r, uint32_t addr) {
    asm volatile("ldmatrix.sync.aligned.m8n8.x4.trans.shared.b16 {%0,%1,%2,%3}, [%4];"
                 : "=r"(r[0]), "=r"(r[1]), "=r"(r[2]), "=r"(r[3]) : "r"(addr));
}
__device__ __forceinline__ uint32_t packh2(float lo, float hi) {
    __half2 h = __floats2half2_rn(lo, hi);
    return *(uint32_t*)&h;
}

// ---------------------------------------------------------------------------
// Kernel 0: fp32 -> fp16 conversion
// ---------------------------------------------------------------------------
__global__ void cvt_fp16_kernel(const float4* __restrict__ in,
                                __half* __restrict__ out, int n4) {
    int i = blockIdx.x * blockDim.x + threadIdx.x;
    if (i >= n4) return;
    float4 v = in[i];
    __half2 a = __floats2half2_rn(v.x, v.y);
    __half2 b = __floats2half2_rn(v.z, v.w);
    *(uint2*)(out + 4 * (size_t)i) = make_uint2(*(uint32_t*)&a, *(uint32_t*)&b);
}

// ---------------------------------------------------------------------------
// Kernel 1: QKV projection, fp16 mma + ldmatrix (EXACT R11-passing shape:
// CTA 128x128, BK=64, 256 thr, 8 warps (4m x 2n), warp tile 32x64).
// Only change: q-scale folds LOG2E for exp2 softmax.
// ---------------------------------------------------------------------------
#define QK_STR 72
#define QT_TILE (128 * QK_STR)
#define QOFF_A1 QT_TILE
#define QOFF_B0 (2 * QT_TILE)
#define QOFF_B1 (3 * QT_TILE)
#define QG_SMEM (4 * QT_TILE * 2)

__global__ __launch_bounds__(256) void qkv_h_kernel(
    const __half* __restrict__ Xh, const __half* __restrict__ Wh,
    const float* __restrict__ bias)
{
    extern __shared__ __half smq[];
    const uint32_t sbase = smem_u32(smq);

    const int tid  = threadIdx.x;
    const int wid  = tid >> 5;
    const int lane = tid & 31;
    const int g    = lane >> 2;
    const int t    = lane & 3;
    const int lr8  = lane & 7;
    const int h8   = (lane >> 3) & 1;
    const int h16  = (lane >> 4) & 1;
    const int warpM = (wid >> 1) * 32;
    const int warpN = (wid & 1) * 64;
    const int mBase = blockIdx.y * 128;
    const int eBase = blockIdx.x * 128;

    auto load_stage = [&](int buf, int s) {
        const int k0 = s * 64;
        #pragma unroll
        for (int c = 0; c < 4; c++) {
            int slot = tid + c * 256;
            int row = slot >> 3;
            int c8  = (slot & 7) * 8;
            cpasync16(sbase + (uint32_t)(((buf ? QOFF_A1 : 0) + row * QK_STR + c8) * 2),
                      Xh + (size_t)(mBase + row) * DIM_ + k0 + c8);
            cpasync16(sbase + (uint32_t)(((buf ? QOFF_B1 : QOFF_B0) + row * QK_STR + c8) * 2),
                      Wh + (size_t)(eBase + row) * DIM_ + k0 + c8);
        }
        asm volatile("cp.async.commit_group;" ::: "memory");
    };

    float acc[2][8][4];
    #pragma unroll
    for (int i = 0; i < 2; i++)
        #pragma unroll
        for (int j = 0; j < 8; j++)
            #pragma unroll
            for (int r = 0; r < 4; r++) acc[i][j][r] = 0.0f;

    load_stage(0, 0);
    load_stage(1, 1);

    const int NS = DIM_ / 64;
    for (int s = 0; s < NS; s++) {
        const int buf = s & 1;
        if (s < NS - 1) asm volatile("cp.async.wait_group 1;" ::: "memory");
        else            asm volatile("cp.async.wait_group 0;" ::: "memory");
        __syncthreads();

        const uint32_t abase = sbase + (uint32_t)((buf ? QOFF_A1 : 0) * 2);
        const uint32_t bbase = sbase + (uint32_t)((buf ? QOFF_B1 : QOFF_B0) * 2);

        #pragma unroll
        for (int kst = 0; kst < 4; kst++) {
            uint32_t aq[2][4];
            #pragma unroll
            for (int mt = 0; mt < 2; mt++)
                ldsm_x4(aq[mt], abase + (uint32_t)(((warpM + 16 * mt + lr8 + 8 * h8) * QK_STR
                                                    + kst * 16 + 8 * h16) * 2));
            #pragma unroll
            for (int ntp = 0; ntp < 4; ntp++) {
                uint32_t bk[4];
                ldsm_x4(bk, bbase + (uint32_t)(((warpN + 16 * ntp + 8 * h16 + lr8) * QK_STR
                                               + kst * 16 + 8 * h8) * 2));
                #pragma unroll
                for (int mt = 0; mt < 2; mt++) {
                    mma16(acc[mt][2 * ntp],     aq[mt][0], aq[mt][1], aq[mt][2], aq[mt][3], bk[0], bk[1]);
                    mma16(acc[mt][2 * ntp + 1], aq[mt][0], aq[mt][1], aq[mt][2], aq[mt][3], bk[2], bk[3]);
                }
            }
        }
        __syncthreads();
        if (s + 2 < NS) load_stage(buf, s + 2);
    }

    #pragma unroll
    for (int nt = 0; nt < 8; nt++) {
        const int c0   = eBase + warpN + nt * 8 + 2 * t;
        const int tsel = c0 >> 10;
        const int rem  = c0 & (DIM_ - 1);
        const int h    = rem >> 6;
        const int hd   = rem & (HD_ - 1);
        __half* dst = (tsel == 0) ? g_q : ((tsel == 1) ? g_k : g_v);
        const float sc = (tsel == 0) ? (SCALE_ * LOG2E_) : 1.0f;
        const float bb0 = __ldg(bias + c0);
        const float bb1 = __ldg(bias + c0 + 1);
        #pragma unroll
        for (int mt = 0; mt < 2; mt++) {
            const int r0 = mBase + warpM + mt * 16 + g;
            #pragma unroll
            for (int half = 0; half < 2; half++) {
                const int row = r0 + half * 8;
                const int bi  = row >> 11;
                const int n   = row & (N_ - 1);
                __half2 hv = __floats2half2_rn(
                    (acc[mt][nt][half * 2 + 0] + bb0) * sc,
                    (acc[mt][nt][half * 2 + 1] + bb1) * sc);
                *(__half2*)(dst + ((((size_t)bi * H_ + h) * N_ + n) * HD_ + hd)) = hv;
            }
        }
    }
}

// ---------------------------------------------------------------------------
// Kernel 2: flash attention (EXACT R11-passing structure; only __expf->exp2f).
// grid (N/128, B*H), 128 thr, 4 warps x 32 q-rows, key tile 64.
// ---------------------------------------------------------------------------
#define QSTRH 72
#define KSTRH 72
#define VSTRH 72
#define HOFF_K (128 * QSTRH)
#define HOFF_V (HOFF_K + 64 * KSTRH)
#define ATT_SMEM ((HOFF_V + 64 * VSTRH) * 2)   // 36864 B

__global__ __launch_bounds__(128, 3) void attn_kernel7(float* __restrict__ out)
{
    extern __shared__ __half smh[];
    __half* Qs = smh;
    const uint32_t sbase = smem_u32(smh);
    const uint32_t kbase = sbase + HOFF_K * 2;
    const uint32_t vbase = sbase + HOFF_V * 2;

    const int tid  = threadIdx.x;
    const int wid  = tid >> 5;
    const int lane = tid & 31;
    const int g    = lane >> 2;
    const int t    = lane & 3;
    const int warpQ = wid * 32;
    const int lr8 = lane & 7;
    const int h8  = (lane >> 3) & 1;
    const int h16 = (lane >> 4) & 1;

    const int bh = blockIdx.y;
    const int bi = bh >> 4;
    const int h  = bh & 15;
    const int q0 = blockIdx.x * 128;

    const __half* Qg = g_q + (size_t)bh * N_ * HD_ + (size_t)q0 * HD_;
    const __half* Kg = g_k + (size_t)bh * N_ * HD_;
    const __half* Vg = g_v + (size_t)bh * N_ * HD_;

    #pragma unroll
    for (int s = 0; s < 8; s++) {
        int slot = tid + s * 128;
        int row = slot >> 3;
        int c8  = (slot & 7) * 8;
        *(float4*)(Qs + row * QSTRH + c8) = *(const float4*)(Qg + row * HD_ + c8);
    }

    float o[2][8][4];
    float mrow[2][2], lrow[2][2];
    #pragma unroll
    for (int mt = 0; mt < 2; mt++) {
        mrow[mt][0] = -1e30f; mrow[mt][1] = -1e30f;
        lrow[mt][0] = 0.0f;   lrow[mt][1] = 0.0f;
        #pragma unroll
        for (int nt = 0; nt < 8; nt++)
            #pragma unroll
            for (int r = 0; r < 4; r++) o[mt][nt][r] = 0.0f;
    }

    for (int kt = 0; kt < N_ / 64; kt++) {
        __syncthreads();
        #pragma unroll
        for (int s = 0; s < 4; s++) {
            int slot = tid + s * 128;
            int row = slot >> 3;
            int c8  = (slot & 7) * 8;
            cpasync16(kbase + (uint32_t)((row * KSTRH + c8) * 2),
                      Kg + (size_t)(kt * 64 + row) * HD_ + c8);
            cpasync16(vbase + (uint32_t)((row * VSTRH + c8) * 2),
                      Vg + (size_t)(kt * 64 + row) * HD_ + c8);
        }
        asm volatile("cp.async.commit_group;" ::: "memory");
        asm volatile("cp.async.wait_group 0;" ::: "memory");
        __syncthreads();

        float s_[2][8][4];
        #pragma unroll
        for (int mt = 0; mt < 2; mt++)
            #pragma unroll
            for (int nt = 0; nt < 8; nt++)
                #pragma unroll
                for (int r = 0; r < 4; r++) s_[mt][nt][r] = 0.0f;

        #pragma unroll
        for (int kst = 0; kst < 4; kst++) {
            uint32_t aq[2][4];
            #pragma unroll
            for (int mt = 0; mt < 2; mt++)
                ldsm_x4(aq[mt], sbase + (uint32_t)(((warpQ + 16 * mt + lr8 + 8 * h8) * QSTRH
                                                    + kst * 16 + 8 * h16) * 2));
            #pragma unroll
            for (int ntp = 0; ntp < 4; ntp++) {
                uint32_t bk[4];
                ldsm_x4(bk, kbase + (uint32_t)(((16 * ntp + 8 * h16 + lr8) * KSTRH
                                               + kst * 16 + 8 * h8) * 2));
                #pragma unroll
                for (int mt = 0; mt < 2; mt++) {
                    mma16(s_[mt][2 * ntp],     aq[mt][0], aq[mt][1], aq[mt][2], aq[mt][3], bk[0], bk[1]);
                    mma16(s_[mt][2 * ntp + 1], aq[mt][0], aq[mt][1], aq[mt][2], aq[mt][3], bk[2], bk[3]);
                }
            }
        }

        // online softmax, base-2 (q pre-scaled by SCALE*log2e)
        #pragma unroll
        for (int mt = 0; mt < 2; mt++) {
            float mx0 = -1e30f, mx1 = -1e30f;
            #pragma unroll
            for (int nt = 0; nt < 8; nt++) {
                mx0 = fmaxf(mx0, fmaxf(s_[mt][nt][0], s_[mt][nt][1]));
                mx1 = fmaxf(mx1, fmaxf(s_[mt][nt][2], s_[mt][nt][3]));
            }
            mx0 = fmaxf(mx0, __shfl_xor_sync(0xffffffffu, mx0, 1));
            mx0 = fmaxf(mx0, __shfl_xor_sync(0xffffffffu, mx0, 2));
            mx1 = fmaxf(mx1, __shfl_xor_sync(0xffffffffu, mx1, 1));
            mx1 = fmaxf(mx1, __shfl_xor_sync(0xffffffffu, mx1, 2));
            const float nm0 = fmaxf(mrow[mt][0], mx0);
            const float nm1 = fmaxf(mrow[mt][1], mx1);
            const float corr0 = exp2f(mrow[mt][0] - nm0);
            const float corr1 = exp2f(mrow[mt][1] - nm1);
            mrow[mt][0] = nm0; mrow[mt][1] = nm1;

            float rs0 = 0.0f, rs1 = 0.0f;
            #pragma unroll
            for (int nt = 0; nt < 8; nt++) {
                float p0 = exp2f(s_[mt][nt][0] - nm0);
                float p1 = exp2f(s_[mt][nt][1] - nm0);
                float p2 = exp2f(s_[mt][nt][2] - nm1);
                float p3 = exp2f(s_[mt][nt][3] - nm1);
                rs0 += p0 + p1;  rs1 += p2 + p3;
                s_[mt][nt][0] = p0; s_[mt][nt][1] = p1;
                s_[mt][nt][2] = p2; s_[mt][nt][3] = p3;
            }
            rs0 += __shfl_xor_sync(0xffffffffu, rs0, 1);
            rs0 += __shfl_xor_sync(0xffffffffu, rs0, 2);
            rs1 += __shfl_xor_sync(0xffffffffu, rs1, 1);
            rs1 += __shfl_xor_sync(0xffffffffu, rs1, 2);
            lrow[mt][0] = lrow[mt][0] * corr0 + rs0;
            lrow[mt][1] = lrow[mt][1] * corr1 + rs1;

            #pragma unroll
            for (int nt = 0; nt < 8; nt++) {
                o[mt][nt][0] *= corr0; o[mt][nt][1] *= corr0;
                o[mt][nt][2] *= corr1; o[mt][nt][3] *= corr1;
            }
        }

        #pragma unroll
        for (int kst = 0; kst < 4; kst++) {
            uint32_t ap[2][4];
            #pragma unroll
            for (int mt = 0; mt < 2; mt++) {
                ap[mt][0] = packh2(s_[mt][2 * kst][0],     s_[mt][2 * kst][1]);
                ap[mt][1] = packh2(s_[mt][2 * kst][2],     s_[mt][2 * kst][3]);
                ap[mt][2] = packh2(s_[mt][2 * kst + 1][0], s_[mt][2 * kst + 1][1]);
                ap[mt][3] = packh2(s_[mt][2 * kst + 1][2], s_[mt][2 * kst + 1][3]);
            }
            #pragma unroll
            for (int ntp = 0; ntp < 4; ntp++) {
                uint32_t bv[4];
                ldsm_x4t(bv, vbase + (uint32_t)(((16 * kst + 8 * h8 + lr8) * VSTRH
                                                + 16 * ntp + 8 * h16) * 2));
                #pragma unroll
                for (int mt = 0; mt < 2; mt++) {
                    mma16(o[mt][2 * ntp],     ap[mt][0], ap[mt][1], ap[mt][2], ap[mt][3], bv[0], bv[1]);
                    mma16(o[mt][2 * ntp + 1], ap[mt][0], ap[mt][1], ap[mt][2], ap[mt][3], bv[2], bv[3]);
                }
            }
        }
    }

    #pragma unroll
    for (int mt = 0; mt < 2; mt++) {
        const float inv0 = 1.0f / lrow[mt][0];
        const float inv1 = 1.0f / lrow[mt][1];
        const int n0 = q0 + warpQ + mt * 16 + g;
        float* po0 = out + ((size_t)bi * N_ + n0) * DIM_ + h * HD_;
        float* po1 = out + ((size_t)bi * N_ + n0 + 8) * DIM_ + h * HD_;
        #pragma unroll
        for (int nt = 0; nt < 8; nt++) {
            const int c = nt * 8 + 2 * t;
            *(float2*)(po0 + c) = make_float2(o[mt][nt][0] * inv0, o[mt][nt][1] * inv0);
            *(float2*)(po1 + c) = make_float2(o[mt][nt][2] * inv1, o[mt][nt][3] * inv1);
        }
    }
}

// ---------------------------------------------------------------------------
extern "C" void kernel_launch(void* const* d_in, const int* in_sizes, int n_in,
                              void* d_out, int out_size)
{
    const float* x    = (const float*)d_in[0];
    const float* wqkv = (const float*)d_in[1];
    const float* bqkv = (const float*)d_in[2];
    float* out = (float*)d_out;

    __half *xh, *wh;
    cudaGetSymbolAddress((void**)&xh, g_xh);
    cudaGetSymbolAddress((void**)&wh, g_wh);

    cudaFuncSetAttribute(qkv_h_kernel,
                         cudaFuncAttributeMaxDynamicSharedMemorySize, QG_SMEM);
    cudaFuncSetAttribute(attn_kernel7,
                         cudaFuncAttributeMaxDynamicSharedMemorySize, ATT_SMEM);

    int n4x = (M_ * DIM_) / 4;
    int n4w = (E3_ * DIM_) / 4;
    cvt_fp16_kernel<<<(n4x + 255) / 256, 256>>>((const float4*)x, xh, n4x);
    cvt_fp16_kernel<<<(n4w + 255) / 256, 256>>>((const float4*)wqkv, wh, n4w);

    dim3 ggrid(E3_ / 128, M_ / 128);   // (24, 64)
    qkv_h_kernel<<<ggrid, 256, QG_SMEM>>>(xh, wh, bqkv);

    dim3 agrid(N_ / 128, B_ * H_);     // (16, 64)
    attn_kernel7<<<agrid, 128, ATT_SMEM>>>(out);
}